// round 8
// baseline (speedup 1.0000x reference)
#include <cuda_runtime.h>
#include <cuda_fp16.h>
#include <cstdint>

#define STATE_DIM 512
#define AFEAT 64
#define HID 256
#define HID2 128
#define KACT 1000
#define NROWS 256000
#define TILE_M 128
#define NTILES 2000            // 256000 / 128

__device__ float g_hstate[256 * HID];

__device__ __forceinline__ uint32_t pk(float lo, float hi) {
    __half2 h = __floats2half2_rn(lo, hi);      // low 16 bits = lo
    return *(uint32_t*)&h;
}
__device__ __forceinline__ uint32_t pkr(float lo, float hi) {
    return pk(fmaxf(lo, 0.f), fmaxf(hi, 0.f));
}

// m16n8k16 f16 MMA, f32 accum, C += A*B (row.col)
__device__ __forceinline__ void mma16(float* c, const uint4& a, uint32_t b0, uint32_t b1) {
    asm volatile("mma.sync.aligned.m16n8k16.row.col.f32.f16.f16.f32 "
        "{%0,%1,%2,%3}, {%4,%5,%6,%7}, {%8,%9}, {%0,%1,%2,%3};"
        : "+f"(c[0]), "+f"(c[1]), "+f"(c[2]), "+f"(c[3])
        : "r"(a.x), "r"(a.y), "r"(a.z), "r"(a.w), "r"(b0), "r"(b1));
}

// ---------------------------------------------------------------------------
// hstate: h_state[b][j] = state[b] . W1[:512,j] + b1[j]   (exact fp32)
// ---------------------------------------------------------------------------
__global__ __launch_bounds__(256) void hstate_kernel(
    const float* __restrict__ state,
    const float* __restrict__ W1,
    const float* __restrict__ b1)
{
    __shared__ float s[4 * STATE_DIM];
    const int b0 = blockIdx.x * 4;
    const int t = threadIdx.x;
    for (int i = t; i < 4 * STATE_DIM; i += 256)
        s[i] = state[b0 * STATE_DIM + i];
    __syncthreads();

    float a0, a1, a2, a3;
    a0 = a1 = a2 = a3 = b1[t];
#pragma unroll 8
    for (int k = 0; k < STATE_DIM; k++) {
        float w = W1[k * HID + t];
        a0 = fmaf(s[k], w, a0);
        a1 = fmaf(s[512 + k], w, a1);
        a2 = fmaf(s[1024 + k], w, a2);
        a3 = fmaf(s[1536 + k], w, a3);
    }
    g_hstate[(b0 + 0) * HID + t] = a0;
    g_hstate[(b0 + 1) * HID + t] = a1;
    g_hstate[(b0 + 2) * HID + t] = a2;
    g_hstate[(b0 + 3) * HID + t] = a3;
}

// ---------------------------------------------------------------------------
// Main fused MLP. 512 threads = 16 warps, 4(M)x4(N) grid, TILE_M=128.
// Each warp: 32 rows (2 m16 frags). L1: 64 cols; L2: 32 cols.
// A1 fragments built directly from gmem (f32 -> f16 cvt), no SMEM staging.
//
// B-frag uint4: x=(n8=0,k0..7) y=(n8=0,k8..15) z=(n8=1,k0..7) w=(n8=1,k8..15)
// A-frag uint4: x=(r,k0..) y=(r+8,k0..) z=(r,k8..) w=(r+8,k8..), f16x2 lo=even k
//
// SMEM (float units):
//  sW2f 16384 | sW1f 8192 | sH1f 16384 | sHS 1024 | sB2 128 | sW3 128 | sOut 128
// ---------------------------------------------------------------------------
#define OFF_W2F 0
#define OFF_W1F 16384
#define OFF_H1F 24576
#define OFF_HS  40960
#define OFF_B2  41984
#define OFF_W3  42112
#define OFF_OUT 42240
#define SMEM_FLOATS 42368
#define SMEM_BYTES (SMEM_FLOATS * 4)

__global__ void __launch_bounds__(512, 1) actor_main(
    const float* __restrict__ af, const float* __restrict__ W1,
    const float* __restrict__ W2, const float* __restrict__ b2,
    const float* __restrict__ W3, const float* __restrict__ b3,
    float* __restrict__ out)
{
    extern __shared__ float sm[];
    uint32_t* sW2f = (uint32_t*)(sm + OFF_W2F);
    uint32_t* sW1f = (uint32_t*)(sm + OFF_W1F);
    uint32_t* sH1f = (uint32_t*)(sm + OFF_H1F);
    float* sHS  = sm + OFF_HS;     // [2][512]
    float* sB2  = sm + OFF_B2;
    float* sW3  = sm + OFF_W3;
    float* sOut = sm + OFF_OUT;

    const int t = threadIdx.x;
    const int lane = t & 31;
    const int w = t >> 5;
    const int mg = w & 3;          // rows mg*32 .. +31
    const int ng = w >> 2;         // L1: cols ng*64..; L2: cols ng*32..

    // ---- build W2 frags: [ng(4)][ks(16)][np(2)][lane(32)] uint4 ----
    for (int i = t; i < 16384; i += 512) {
        int ws = i & 3, ln = (i >> 2) & 31;
        int np = (i >> 7) & 1, ks = (i >> 8) & 15, g = (i >> 12) & 3;
        int krow = ks * 16 + (ws & 1) * 8 + (ln & 3) * 2;
        int col  = g * 32 + np * 16 + (ws >> 1) * 8 + (ln >> 2);
        sW2f[i] = pk(W2[krow * HID2 + col], W2[(krow + 1) * HID2 + col]);
    }
    // ---- build W1a frags: [ng(4)][ks(4)][np(4)][lane(32)] uint4 ----
    for (int i = t; i < 8192; i += 512) {
        int ws = i & 3, ln = (i >> 2) & 31;
        int np = (i >> 7) & 3, ks = (i >> 9) & 3, g = (i >> 11) & 3;
        int krow = STATE_DIM + ks * 16 + (ws & 1) * 8 + (ln & 3) * 2;
        int col  = g * 64 + np * 16 + (ws >> 1) * 8 + (ln >> 2);
        sW1f[i] = pk(W1[krow * HID + col], W1[(krow + 1) * HID + col]);
    }
    if (t < 128) { sB2[t] = b2[t]; sW3[t] = W3[t]; sOut[t] = 0.f; }

    auto stage_hs = [&](int tl, int buf) {
        int r0 = tl * TILE_M;
        int blo = r0 / KACT;
        int bhi = (r0 + TILE_M - 1) / KACT;
        sHS[buf * 512 + t] = g_hstate[(t < 256 ? blo : bhi) * HID + (t & 255)];
    };

    // ---- prologue ----
    int tile = blockIdx.x;
    stage_hs(tile, 0);
    __syncthreads();

    const float bias3 = __ldg(b3);
    const uint4* w1v = (const uint4*)sW1f;
    const uint4* w2v = (const uint4*)sW2f;
    const uint4* h1v = (const uint4*)sH1f;

    // A1 gmem base for this warp-lane (row/col within tile fixed per lane)
    const int a_row = mg * 32 + (lane >> 2);           // + mf*16, +8 variants
    const int a_col = (lane & 3) * 2;                  // + ks*16, +8 variants

    int it = 0;
    for (; tile < NTILES; tile += gridDim.x, it++) {
        const int row0 = tile * TILE_M;
        const int ntile = tile + gridDim.x;
        const int cur = it & 1, nxt = cur ^ 1;
        const int split = (row0 / KACT + 1) * KACT - row0;

        // ---- L1: C = af @ W1a, init C = h_state (exact fp32) ----
        // C-frag: bit0 = col parity, bit1 = row+8
        float acc[2][8][4];
        const float* hsc = sHS + cur * 512;
#pragma unroll
        for (int mf = 0; mf < 2; mf++) {
            const int r = mg * 32 + mf * 16 + (lane >> 2);
#pragma unroll
            for (int nt = 0; nt < 8; nt++)
#pragma unroll
            for (int rg = 0; rg < 4; rg++) {
                int rr = r + (rg >> 1) * 8;
                int c = ng * 64 + nt * 8 + 2 * (lane & 3) + (rg & 1);
                acc[mf][nt][rg] = hsc[(rr >= split ? 256 : 0) + c];
            }
        }
#pragma unroll
        for (int ks = 0; ks < 4; ks++) {
            uint4 a[2];
#pragma unroll
            for (int mf = 0; mf < 2; mf++) {
                const float* p = af + (size_t)(row0 + a_row + mf * 16) * AFEAT
                                    + ks * 16 + a_col;
                float2 v0 = *(const float2*)(p);
                float2 v1 = *(const float2*)(p + 8 * AFEAT);
                float2 v2 = *(const float2*)(p + 8);
                float2 v3 = *(const float2*)(p + 8 * AFEAT + 8);
                a[mf].x = pk(v0.x, v0.y);
                a[mf].y = pk(v1.x, v1.y);
                a[mf].z = pk(v2.x, v2.y);
                a[mf].w = pk(v3.x, v3.y);
            }
#pragma unroll
            for (int np = 0; np < 4; np++) {
                uint4 b = w1v[((ng * 4 + ks) * 4 + np) * 32 + lane];
                mma16(acc[0][np * 2],     a[0], b.x, b.y);
                mma16(acc[0][np * 2 + 1], a[0], b.z, b.w);
                mma16(acc[1][np * 2],     a[1], b.x, b.y);
                mma16(acc[1][np * 2 + 1], a[1], b.z, b.w);
            }
        }
        // ---- ep1: relu -> f16 pairs -> sH1f as L2 A-frags ----
        // sH1f: [m16(8)][k16(16)][lane] uint4
#pragma unroll
        for (int mf = 0; mf < 2; mf++)
#pragma unroll
        for (int q = 0; q < 4; q++) {
            uint4 v;
            v.x = pkr(acc[mf][2 * q][0],     acc[mf][2 * q][1]);
            v.y = pkr(acc[mf][2 * q][2],     acc[mf][2 * q][3]);
            v.z = pkr(acc[mf][2 * q + 1][0], acc[mf][2 * q + 1][1]);
            v.w = pkr(acc[mf][2 * q + 1][2], acc[mf][2 * q + 1][3]);
            ((uint4*)sH1f)[((mg * 2 + mf) * 16 + ng * 4 + q) * 32 + lane] = v;
        }
        __syncthreads();   // S1: h1 ready

        // ---- stage next tile's h_state while L2 runs ----
        if (ntile < NTILES) stage_hs(ntile, nxt);

        // ---- L2: C2 = h1 @ W2 ----
        float acc2[2][4][4];
#pragma unroll
        for (int mf = 0; mf < 2; mf++)
#pragma unroll
        for (int nt = 0; nt < 4; nt++)
#pragma unroll
        for (int rg = 0; rg < 4; rg++) acc2[mf][nt][rg] = 0.f;
#pragma unroll
        for (int ks = 0; ks < 16; ks++) {
            uint4 a0 = h1v[((mg * 2 + 0) * 16 + ks) * 32 + lane];
            uint4 a1 = h1v[((mg * 2 + 1) * 16 + ks) * 32 + lane];
#pragma unroll
            for (int np = 0; np < 2; np++) {
                uint4 b = w2v[((ng * 16 + ks) * 2 + np) * 32 + lane];
                mma16(acc2[0][np * 2],     a0, b.x, b.y);
                mma16(acc2[0][np * 2 + 1], a0, b.z, b.w);
                mma16(acc2[1][np * 2],     a1, b.x, b.y);
                mma16(acc2[1][np * 2 + 1], a1, b.z, b.w);
            }
        }

        // ---- L3: out = relu(C2 + b2) . W3 + b3 ----
#pragma unroll
        for (int mf = 0; mf < 2; mf++) {
            float part[2] = {0.f, 0.f};
#pragma unroll
            for (int nt = 0; nt < 4; nt++)
#pragma unroll
            for (int rg = 0; rg < 4; rg++) {
                int c = ng * 32 + nt * 8 + 2 * (lane & 3) + (rg & 1);
                float v = fmaxf(acc2[mf][nt][rg] + sB2[c], 0.f);
                part[rg >> 1] += v * sW3[c];
            }
#pragma unroll
            for (int rb = 0; rb < 2; rb++) {
                float v = part[rb];
                v += __shfl_xor_sync(0xffffffffu, v, 1);
                v += __shfl_xor_sync(0xffffffffu, v, 2);
                if ((lane & 3) == 0)
                    atomicAdd(&sOut[mg * 32 + mf * 16 + rb * 8 + (lane >> 2)], v);
            }
        }
        __syncthreads();   // S2: L3 atomics done, h1 reads done
        if (t < 128) {
            out[row0 + t] = sOut[t] + bias3;
            sOut[t] = 0.f;
        }
        __syncthreads();   // S3: buffers free
    }
}

// ---------------------------------------------------------------------------
extern "C" void kernel_launch(void* const* d_in, const int* in_sizes, int n_in,
                              void* d_out, int out_size)
{
    const float* state = (const float*)d_in[0];
    const float* afeats = (const float*)d_in[1];
    const float* W1    = (const float*)d_in[2];
    const float* b1    = (const float*)d_in[3];
    const float* W2    = (const float*)d_in[4];
    const float* b2    = (const float*)d_in[5];
    const float* W3    = (const float*)d_in[6];
    const float* b3    = (const float*)d_in[7];
    float* out = (float*)d_out;
    (void)in_sizes; (void)n_in; (void)out_size;

    static int sm_count = 0;
    if (sm_count == 0) {
        cudaDeviceGetAttribute(&sm_count, cudaDevAttrMultiProcessorCount, 0);
        if (sm_count <= 0) sm_count = 148;
        cudaFuncSetAttribute(actor_main,
                             cudaFuncAttributeMaxDynamicSharedMemorySize, SMEM_BYTES);
    }

    hstate_kernel<<<64, 256>>>(state, W1, b1);
    actor_main<<<sm_count, 512, SMEM_BYTES>>>(afeats, W1, W2, b2, W3, b3, out);
}